// round 15
// baseline (speedup 1.0000x reference)
#include <cuda_runtime.h>
#include <cuda.h>
#include <stdint.h>

// StationSelectionAggregator:
//   schedule: [B, WIN, N_ST]  one-hot float32
//   csi:      [B, N_ST, N_SUB, WIN] float32
//   out:      [B, WIN, N_SUB] float32
//   out[b,w,s] = csi[b, t(b,w), s, w]  (exact selection; schedule one-hot).
//
// R15: read side is plateaued (6.89-6.97 TB/s over 5 TMA variants). This
// round moves the WRITE stream to TMA: selected tile staged in smem in exact
// [w][s] output layout, flushed with one bulk tensor store per CTA (async,
// no STG instructions, no L1 write path). Thread mapping re-derived so both
// the stage reads (bank = w) and otile writes (bank = 16*(l&1)+s, s distinct
// per parity group) are conflict-free.
#define B_    32
#define NST   8
#define NSUB  256
#define WIN   2048

__device__ __forceinline__ uint32_t smem_u32(const void* p) {
    uint32_t a;
    asm("{ .reg .u64 t; cvta.to.shared.u64 t, %1; cvt.u32.u64 %0, t; }"
        : "=r"(a) : "l"(p));
    return a;
}

__device__ __forceinline__ void mbar_wait0(uint32_t mb) {
    uint32_t done;
    asm volatile("{\n\t.reg .pred p;\n\t"
                 "mbarrier.try_wait.parity.acquire.cta.shared::cta.b64 p, [%1], %2;\n\t"
                 "selp.b32 %0, 1, 0, p;\n\t}"
                 : "=r"(done) : "r"(mb), "r"(0u) : "memory");
    if (!done) {
        asm volatile("{\n\t.reg .pred P1;\n\t"
                     "WL_%=:\n\t"
                     "mbarrier.try_wait.parity.acquire.cta.shared::cta.b64 P1, [%0], %1, 0x989680;\n\t"
                     "@P1 bra.uni WD_%=;\n\t"
                     "bra.uni WL_%=;\n\t"
                     "WD_%=:\n\t}"
                     :: "r"(mb), "r"(0u) : "memory");
    }
}

// ---- TMA-in + TMA-out kernel: box [32w][16s][8t] in, [16s][32w] out ----
__global__ __launch_bounds__(256)
void station_select_tma2_kernel(const __grid_constant__ CUtensorMap tin,
                                const __grid_constant__ CUtensorMap tout,
                                const float* __restrict__ sched) {
    // blockIdx.x : w tile (64, fastest), .y : s tile (16), .z : batch (32)
    __shared__ __align__(128) float stage[NST][16][32];  // 16 KB TMA dest
    __shared__ __align__(128) float otile[32][16];       // 2 KB TMA src, exact [w][s]
    __shared__ int   tw[32];
    __shared__ __align__(8) uint64_t mbar;

    const int b   = blockIdx.z;
    const int w0  = blockIdx.x * 32;
    const int s0  = blockIdx.y * 16;
    const int tid = threadIdx.x;     // 0..255
    const int l   = tid & 31;
    const int k   = tid >> 5;        // warp 0..7

    const uint32_t mb = smem_u32(&mbar);

    if (tid == 0) {
        asm volatile("mbarrier.init.shared.b64 [%0], %1;"
                     :: "r"(mb), "r"(1) : "memory");
        asm volatile("mbarrier.arrive.expect_tx.shared.b64 _, [%0], %1;"
                     :: "r"(mb), "r"((uint32_t)(NST * 16 * 32 * 4)) : "memory");
        asm volatile("cp.async.bulk.tensor.3d.shared::cta.global.tile.mbarrier::complete_tx::bytes "
                     "[%0], [%1, {%2, %3, %4}], [%5];"
                     :: "r"(smem_u32(stage)), "l"(&tin),
                        "r"(w0), "r"(s0), "r"(b * NST), "r"(mb)
                     : "memory");
    }
    // station decode overlaps the TMA fill (exact: one-hot values are 0.0/1.0)
    if (tid < 32) {
        const float4* sp = reinterpret_cast<const float4*>(
            sched + ((size_t)b * WIN + (size_t)(w0 + tid)) * NST);
        const float4 a = sp[0];
        const float4 c = sp[1];
        const float tf = a.y + 2.f * a.z + 3.f * a.w +
                         4.f * c.x + 5.f * c.y + 6.f * c.z + 7.f * c.w;
        tw[tid] = (int)(tf + 0.5f);
    }
    __syncthreads();   // publishes mbar init + tw

    mbar_wait0(mb);

    // select + layout-transform. Thread (k,l): w = l,
    //   s1 = (2k + (l>>1)) & 15,  s2 = (s1 + 1) & 15.
    // stage read bank = w & 31 = l (row stride 32 == 0 mod 32)  -> clean.
    // otile write bank = (16*w + s)&31 = 16*(l&1) + s; within each 16-lane
    // parity group s is a bijection mod 16 -> 32 distinct banks. Coverage:
    // per w, k spans one parity class of s, +1 spans the other -> all 16.
    const int w  = l;
    const int s1 = (2 * k + (l >> 1)) & 15;
    const int s2 = (s1 + 1) & 15;
    const int t  = tw[w];
    const float va = stage[t][s1][w];
    const float vb = stage[t][s2][w];
    otile[w][s1] = va;
    otile[w][s2] = vb;
    __syncthreads();

    // bulk tensor store: out viewed as [s][w][b], coords {s0, w0, b}
    if (tid == 0) {
        asm volatile("fence.proxy.async;" ::: "memory");
        asm volatile("cp.async.bulk.tensor.3d.global.shared::cta.tile.bulk_group "
                     "[%0, {%1, %2, %3}], [%4];"
                     :: "l"(&tout), "r"(s0), "r"(w0), "r"(b),
                        "r"(smem_u32(otile)) : "memory");
        asm volatile("cp.async.bulk.commit_group;" ::: "memory");
        asm volatile("cp.async.bulk.wait_group.read 0;" ::: "memory");
    }
}

// ---------------- fallback: R1 LDG kernel ----------------
__global__ __launch_bounds__(256)
void station_select_ldg_kernel(const float* __restrict__ sched,
                               const float* __restrict__ csi,
                               float* __restrict__ out) {
    __shared__ float tile[32][33];
    __shared__ int   tw[32];

    const int b   = blockIdx.z;
    const int w0  = blockIdx.x * 32;
    const int s0  = blockIdx.y * 32;
    const int tid = threadIdx.x;
    const int tx  = tid & 31;
    const int ty  = tid >> 5;

    if (tid < 32) {
        const float4* sp = reinterpret_cast<const float4*>(
            sched + ((size_t)b * WIN + (size_t)(w0 + tid)) * NST);
        const float4 a = sp[0];
        const float4 c = sp[1];
        const float tf = a.y + 2.f * a.z + 3.f * a.w +
                         4.f * c.x + 5.f * c.y + 6.f * c.z + 7.f * c.w;
        tw[tid] = (int)(tf + 0.5f);
    }
    __syncthreads();

    const int t = tw[tx];
    const float* p = csi + ((size_t)(b * NST + t) * NSUB + (size_t)s0) * WIN
                         + (size_t)(w0 + tx);
    float v[4];
#pragma unroll
    for (int r = 0; r < 4; r++)
        v[r] = p[(size_t)(ty + r * 8) * WIN];
#pragma unroll
    for (int r = 0; r < 4; r++)
        tile[ty + r * 8][tx] = v[r];
    __syncthreads();

#pragma unroll
    for (int r = 0; r < 4; r++) {
        const int wl = ty + r * 8;
        out[((size_t)b * WIN + (size_t)(w0 + wl)) * NSUB + (size_t)(s0 + tx)]
            = tile[tx][wl];
    }
}

// ---------------- host ----------------
typedef CUresult (*tmap_encode_fn)(
    CUtensorMap*, CUtensorMapDataType, cuuint32_t, void*,
    const cuuint64_t*, const cuuint64_t*, const cuuint32_t*, const cuuint32_t*,
    CUtensorMapInterleave, CUtensorMapSwizzle, CUtensorMapL2promotion,
    CUtensorMapFloatOOBfill);

extern "C" void kernel_launch(void* const* d_in, const int* in_sizes, int n_in,
                              void* d_out, int out_size) {
    const float* sched = (const float*)d_in[0];
    const float* csi   = (const float*)d_in[1];
    if (n_in >= 2 && in_sizes[0] != 524288) {   // schedule = 32*2048*8 elems
        sched = (const float*)d_in[1];
        csi   = (const float*)d_in[0];
    }
    float* out = (float*)d_out;

    void* fn = nullptr;
    cudaDriverEntryPointQueryResult qr = cudaDriverEntryPointSymbolNotFound;
#if CUDART_VERSION >= 12050
    cudaGetDriverEntryPointByVersion("cuTensorMapEncodeTiled", &fn, 12000,
                                     cudaEnableDefault, &qr);
#else
    cudaGetDriverEntryPoint("cuTensorMapEncodeTiled", &fn,
                            cudaEnableDefault, &qr);
#endif
    bool ok = false;
    CUtensorMap tin, tout;
    if (fn != nullptr && qr == cudaDriverEntryPointSuccess) {
        tmap_encode_fn enc = (tmap_encode_fn)fn;
        // input: csi viewed as [w=2048][s=256][plane=256(=b*8+t)]
        {
            cuuint64_t dims[3]    = {WIN, NSUB, (cuuint64_t)B_ * NST};
            cuuint64_t strides[2] = {(cuuint64_t)WIN * 4,
                                     (cuuint64_t)WIN * NSUB * 4};
            cuuint32_t box[3]     = {32, 16, NST};
            cuuint32_t es[3]      = {1, 1, 1};
            ok = enc(&tin, CU_TENSOR_MAP_DATA_TYPE_FLOAT32, 3,
                     (void*)csi, dims, strides, box, es,
                     CU_TENSOR_MAP_INTERLEAVE_NONE,
                     CU_TENSOR_MAP_SWIZZLE_NONE,
                     CU_TENSOR_MAP_L2_PROMOTION_L2_128B,
                     CU_TENSOR_MAP_FLOAT_OOB_FILL_NONE) == CUDA_SUCCESS;
        }
        // output: out viewed as [s=256][w=2048][b=32]
        if (ok) {
            cuuint64_t dims[3]    = {NSUB, WIN, B_};
            cuuint64_t strides[2] = {(cuuint64_t)NSUB * 4,
                                     (cuuint64_t)NSUB * WIN * 4};
            cuuint32_t box[3]     = {16, 32, 1};
            cuuint32_t es[3]      = {1, 1, 1};
            ok = enc(&tout, CU_TENSOR_MAP_DATA_TYPE_FLOAT32, 3,
                     (void*)out, dims, strides, box, es,
                     CU_TENSOR_MAP_INTERLEAVE_NONE,
                     CU_TENSOR_MAP_SWIZZLE_NONE,
                     CU_TENSOR_MAP_L2_PROMOTION_L2_128B,
                     CU_TENSOR_MAP_FLOAT_OOB_FILL_NONE) == CUDA_SUCCESS;
        }
    }

    if (ok) {
        dim3 grid(WIN / 32, NSUB / 16, B_);
        station_select_tma2_kernel<<<grid, 256>>>(tin, tout, sched);
    } else {
        dim3 grid(WIN / 32, NSUB / 32, B_);
        station_select_ldg_kernel<<<grid, 256>>>(sched, csi, out);
    }
}

// round 16
// speedup vs baseline: 1.0271x; 1.0271x over previous
#include <cuda_runtime.h>
#include <cuda.h>
#include <stdint.h>

// StationSelectionAggregator:
//   schedule: [B, WIN, N_ST]  one-hot float32
//   csi:      [B, N_ST, N_SUB, WIN] float32
//   out:      [B, WIN, N_SUB] float32
//   out[b,w,s] = csi[b, t(b,w), s, w]  (exact selection; schedule one-hot).
//
// R16 = R12 (best config: one-shot TMA box [32w][16s][8t], 256 thr,
// 8 CTAs/SM, 6.97 TB/s) with L2_PROMOTION_256B: adjacent concurrent CTAs
// own adjacent 128B halves of each 256B fetch, so promotion converts the
// neighbor's DRAM access into an L2 hit and doubles DRAM burst runs at
// unchanged occupancy. Write-TMA (R15), pipelining (R11), LDG variants
// (R1-R9) all regressed and stay excluded.
#define B_    32
#define NST   8
#define NSUB  256
#define WIN   2048

__device__ __forceinline__ uint32_t smem_u32(const void* p) {
    uint32_t a;
    asm("{ .reg .u64 t; cvta.to.shared.u64 t, %1; cvt.u32.u64 %0, t; }"
        : "=r"(a) : "l"(p));
    return a;
}

__device__ __forceinline__ void mbar_wait0(uint32_t mb) {
    uint32_t done;
    asm volatile("{\n\t.reg .pred p;\n\t"
                 "mbarrier.try_wait.parity.acquire.cta.shared::cta.b64 p, [%1], %2;\n\t"
                 "selp.b32 %0, 1, 0, p;\n\t}"
                 : "=r"(done) : "r"(mb), "r"(0u) : "memory");
    if (!done) {
        asm volatile("{\n\t.reg .pred P1;\n\t"
                     "WL_%=:\n\t"
                     "mbarrier.try_wait.parity.acquire.cta.shared::cta.b64 P1, [%0], %1, 0x989680;\n\t"
                     "@P1 bra.uni WD_%=;\n\t"
                     "bra.uni WL_%=;\n\t"
                     "WD_%=:\n\t}"
                     :: "r"(mb), "r"(0u) : "memory");
    }
}

// ---------------- one-shot TMA kernel, 16 KB box ----------------
__global__ __launch_bounds__(256)
void station_select_tma_kernel(const __grid_constant__ CUtensorMap tmap,
                               const float* __restrict__ sched,
                               float* __restrict__ out) {
    // blockIdx.x : w tile (64, fastest), .y : s tile (16), .z : batch (32)
    __shared__ __align__(128) float stage[NST][16][32];  // 16 KB TMA dest
    __shared__ float tile[16][34];                       // stride 34: conflict-free both phases
    __shared__ int   tw[32];
    __shared__ __align__(8) uint64_t mbar;

    const int b   = blockIdx.z;
    const int w0  = blockIdx.x * 32;
    const int s0  = blockIdx.y * 16;
    const int tid = threadIdx.x;
    const int tx  = tid & 31;
    const int ty  = tid >> 5;        // 0..7

    const uint32_t mb = smem_u32(&mbar);

    if (tid == 0) {
        asm volatile("mbarrier.init.shared.b64 [%0], %1;"
                     :: "r"(mb), "r"(1) : "memory");
        asm volatile("mbarrier.arrive.expect_tx.shared.b64 _, [%0], %1;"
                     :: "r"(mb), "r"((uint32_t)(NST * 16 * 32 * 4)) : "memory");
        asm volatile("cp.async.bulk.tensor.3d.shared::cta.global.tile.mbarrier::complete_tx::bytes "
                     "[%0], [%1, {%2, %3, %4}], [%5];"
                     :: "r"(smem_u32(stage)), "l"(&tmap),
                        "r"(w0), "r"(s0), "r"(b * NST), "r"(mb)
                     : "memory");
    }
    // station decode overlaps the TMA fill (exact: one-hot values are 0.0/1.0)
    if (tid < 32) {
        const float4* sp = reinterpret_cast<const float4*>(
            sched + ((size_t)b * WIN + (size_t)(w0 + tid)) * NST);
        const float4 a = sp[0];
        const float4 c = sp[1];
        const float tf = a.y + 2.f * a.z + 3.f * a.w +
                         4.f * c.x + 5.f * c.y + 6.f * c.z + 7.f * c.w;
        tw[tid] = (int)(tf + 0.5f);
    }
    __syncthreads();   // publishes mbar init + tw

    mbar_wait0(mb);

    // smem select: addr%128 == 4*tx -> conflict-free for any plane t
    const int t = tw[tx];
    const float v0 = stage[t][ty][tx];
    const float v1 = stage[t][ty + 8][tx];

    // transpose tile (stride 34): write banks (2*ty + tx)&31 all distinct
    tile[ty][tx]     = v0;
    tile[ty + 8][tx] = v1;
    __syncthreads();

    // stores: warp ty covers w rows 4*ty..4*ty+3; lanes split into two
    // 16-wide halves over s. read banks (2*sl + wl): even/odd disjoint.
    const int h  = tx >> 4;          // 0/1 -> which w row in the pair
    const int sl = tx & 15;          // s within tile
#pragma unroll
    for (int rr = 0; rr < 2; rr++) {
        const int wl = 4 * ty + 2 * rr + h;
        out[((size_t)b * WIN + (size_t)(w0 + wl)) * NSUB + (size_t)(s0 + sl)]
            = tile[sl][wl];
    }
}

// ---------------- fallback: R1 LDG kernel ----------------
__global__ __launch_bounds__(256)
void station_select_ldg_kernel(const float* __restrict__ sched,
                               const float* __restrict__ csi,
                               float* __restrict__ out) {
    __shared__ float tile[32][33];
    __shared__ int   tw[32];

    const int b   = blockIdx.z;
    const int w0  = blockIdx.x * 32;
    const int s0  = blockIdx.y * 32;
    const int tid = threadIdx.x;
    const int tx  = tid & 31;
    const int ty  = tid >> 5;

    if (tid < 32) {
        const float4* sp = reinterpret_cast<const float4*>(
            sched + ((size_t)b * WIN + (size_t)(w0 + tid)) * NST);
        const float4 a = sp[0];
        const float4 c = sp[1];
        const float tf = a.y + 2.f * a.z + 3.f * a.w +
                         4.f * c.x + 5.f * c.y + 6.f * c.z + 7.f * c.w;
        tw[tid] = (int)(tf + 0.5f);
    }
    __syncthreads();

    const int t = tw[tx];
    const float* p = csi + ((size_t)(b * NST + t) * NSUB + (size_t)s0) * WIN
                         + (size_t)(w0 + tx);
    float v[4];
#pragma unroll
    for (int r = 0; r < 4; r++)
        v[r] = p[(size_t)(ty + r * 8) * WIN];
#pragma unroll
    for (int r = 0; r < 4; r++)
        tile[ty + r * 8][tx] = v[r];
    __syncthreads();

#pragma unroll
    for (int r = 0; r < 4; r++) {
        const int wl = ty + r * 8;
        out[((size_t)b * WIN + (size_t)(w0 + wl)) * NSUB + (size_t)(s0 + tx)]
            = tile[tx][wl];
    }
}

// ---------------- host ----------------
typedef CUresult (*tmap_encode_fn)(
    CUtensorMap*, CUtensorMapDataType, cuuint32_t, void*,
    const cuuint64_t*, const cuuint64_t*, const cuuint32_t*, const cuuint32_t*,
    CUtensorMapInterleave, CUtensorMapSwizzle, CUtensorMapL2promotion,
    CUtensorMapFloatOOBfill);

extern "C" void kernel_launch(void* const* d_in, const int* in_sizes, int n_in,
                              void* d_out, int out_size) {
    const float* sched = (const float*)d_in[0];
    const float* csi   = (const float*)d_in[1];
    if (n_in >= 2 && in_sizes[0] != 524288) {   // schedule = 32*2048*8 elems
        sched = (const float*)d_in[1];
        csi   = (const float*)d_in[0];
    }
    float* out = (float*)d_out;

    // tensormap: csi viewed as [w=2048][s=256][plane=256(=b*8+t)]
    void* fn = nullptr;
    cudaDriverEntryPointQueryResult qr = cudaDriverEntryPointSymbolNotFound;
#if CUDART_VERSION >= 12050
    cudaGetDriverEntryPointByVersion("cuTensorMapEncodeTiled", &fn, 12000,
                                     cudaEnableDefault, &qr);
#else
    cudaGetDriverEntryPoint("cuTensorMapEncodeTiled", &fn,
                            cudaEnableDefault, &qr);
#endif
    bool ok = false;
    CUtensorMap tmap;
    if (fn != nullptr && qr == cudaDriverEntryPointSuccess) {
        cuuint64_t dims[3]    = {WIN, NSUB, (cuuint64_t)B_ * NST};
        cuuint64_t strides[2] = {(cuuint64_t)WIN * 4,
                                 (cuuint64_t)WIN * NSUB * 4};
        cuuint32_t box[3]     = {32, 16, NST};
        cuuint32_t es[3]      = {1, 1, 1};
        ok = ((tmap_encode_fn)fn)(&tmap, CU_TENSOR_MAP_DATA_TYPE_FLOAT32, 3,
                                  (void*)csi, dims, strides, box, es,
                                  CU_TENSOR_MAP_INTERLEAVE_NONE,
                                  CU_TENSOR_MAP_SWIZZLE_NONE,
                                  CU_TENSOR_MAP_L2_PROMOTION_L2_256B,
                                  CU_TENSOR_MAP_FLOAT_OOB_FILL_NONE)
             == CUDA_SUCCESS;
    }

    if (ok) {
        dim3 grid(WIN / 32, NSUB / 16, B_);
        station_select_tma_kernel<<<grid, 256>>>(tmap, sched, out);
    } else {
        dim3 grid(WIN / 32, NSUB / 32, B_);
        station_select_ldg_kernel<<<grid, 256>>>(sched, csi, out);
    }
}